// round 1
// baseline (speedup 1.0000x reference)
#include <cuda_runtime.h>
#include <math.h>

// Problem constants (match reference setup_inputs)
#define NN 100000
#define EE 1600000
#define IN_FEAT 512
#define HID 128
#define NC 7

// -------- scratch (device globals; allocation-free rule) --------
__device__ __align__(256) float g_dinv[NN];          // deg -> rsqrt(deg)
__device__ __align__(256) float g_h1[(size_t)NN * HID];   // x @ W1
__device__ __align__(256) float g_out1[(size_t)NN * HID]; // aggregated layer1
__device__ __align__(256) float g_h2[(size_t)NN * 8];     // elu(out1+b1) @ W2, padded to 8
__device__ __align__(256) float g_out2[(size_t)NN * 8];   // aggregated layer2 (padded)

// ---------------- degree ----------------
__global__ void k_deg_init(int n) {
    int i = blockIdx.x * blockDim.x + threadIdx.x;
    if (i < n) g_dinv[i] = 1.0f;  // self-loop weight
}

__global__ void k_deg_acc(const int* __restrict__ ei, const float* __restrict__ ew, int E) {
    int e = blockIdx.x * blockDim.x + threadIdx.x;
    if (e < E) atomicAdd(&g_dinv[ei[E + e]], ew[e]);
}

__global__ void k_dinv(int n) {
    int i = blockIdx.x * blockDim.x + threadIdx.x;
    if (i < n) {
        float d = g_dinv[i];
        g_dinv[i] = d > 0.0f ? rsqrtf(d) : 0.0f;
    }
}

// ---------------- GEMM1: h1 = x @ W1  (M x 512) @ (512 x 128) ----------------
// BM=128, BN=128(full), BK=16, 256 threads, 8x8 per thread
__global__ void __launch_bounds__(256) k_gemm1(const float* __restrict__ A,
                                               const float* __restrict__ B,
                                               int M) {
    __shared__ float As[16][128];
    __shared__ float Bs[16][128];

    const int tid = threadIdx.x;
    const int tx = tid & 15;        // 0..15 -> col group
    const int ty = tid >> 4;        // 0..15 -> row group
    const int rowBase = blockIdx.x * 128;

    float acc[8][8];
#pragma unroll
    for (int i = 0; i < 8; i++)
#pragma unroll
        for (int j = 0; j < 8; j++) acc[i][j] = 0.0f;

    for (int k0 = 0; k0 < IN_FEAT; k0 += 16) {
        // load A tile: 128 rows x 16 cols = 512 float4
#pragma unroll
        for (int l = 0; l < 2; l++) {
            int idx = tid + l * 256;
            int r = idx >> 2;           // row in tile 0..127
            int g = idx & 3;            // col group 0..3
            int grow = rowBase + r;
            float4 v = make_float4(0.f, 0.f, 0.f, 0.f);
            if (grow < M)
                v = *(const float4*)(A + (size_t)grow * IN_FEAT + k0 + g * 4);
            As[g * 4 + 0][r] = v.x;
            As[g * 4 + 1][r] = v.y;
            As[g * 4 + 2][r] = v.z;
            As[g * 4 + 3][r] = v.w;
        }
        // load B tile: 16 rows x 128 cols = 512 float4
#pragma unroll
        for (int l = 0; l < 2; l++) {
            int idx = tid + l * 256;
            int r = idx >> 5;           // 0..15
            int c = (idx & 31) << 2;    // 0..124
            *(float4*)&Bs[r][c] = *(const float4*)(B + (size_t)(k0 + r) * HID + c);
        }
        __syncthreads();

#pragma unroll
        for (int k = 0; k < 16; k++) {
            float a[8], b[8];
            *(float4*)&a[0] = *(const float4*)&As[k][ty * 8];
            *(float4*)&a[4] = *(const float4*)&As[k][ty * 8 + 4];
            *(float4*)&b[0] = *(const float4*)&Bs[k][tx * 8];
            *(float4*)&b[4] = *(const float4*)&Bs[k][tx * 8 + 4];
#pragma unroll
            for (int i = 0; i < 8; i++)
#pragma unroll
                for (int j = 0; j < 8; j++) acc[i][j] += a[i] * b[j];
        }
        __syncthreads();
    }

    // store
#pragma unroll
    for (int i = 0; i < 8; i++) {
        int grow = rowBase + ty * 8 + i;
        if (grow < M) {
            float* cp = g_h1 + (size_t)grow * HID + tx * 8;
            *(float4*)(cp)     = *(float4*)&acc[i][0];
            *(float4*)(cp + 4) = *(float4*)&acc[i][4];
        }
    }
}

// ---------------- self-loop init: out1 = h1 * dinv^2 ----------------
__global__ void k_self1(int n) {
    size_t idx = (size_t)blockIdx.x * blockDim.x + threadIdx.x;
    if (idx < (size_t)n * HID) {
        int i = (int)(idx >> 7);
        float d = g_dinv[i];
        g_out1[idx] = g_h1[idx] * d * d;
    }
}

// ---------------- edge scatter layer 1: warp per edge, red.v4 ----------------
__global__ void k_scatter1(const int* __restrict__ ei, const float* __restrict__ ew, int E) {
    int warp = (int)(((size_t)blockIdx.x * blockDim.x + threadIdx.x) >> 5);
    int lane = threadIdx.x & 31;
    if (warp >= E) return;
    int s = ei[warp];
    int d = ei[E + warp];
    float norm = g_dinv[s] * ew[warp] * g_dinv[d];
    float4 v = *((const float4*)(g_h1 + (size_t)s * HID) + lane);
    float* p = g_out1 + (size_t)d * HID + lane * 4;
    asm volatile("red.global.add.v4.f32 [%0], {%1,%2,%3,%4};"
                 :: "l"(p), "f"(v.x * norm), "f"(v.y * norm), "f"(v.z * norm), "f"(v.w * norm)
                 : "memory");
}

// ---------------- fused: h = elu(out1 + b1); h2 = h @ W2 (warp per node) ----------------
__global__ void k_fuse2(const float* __restrict__ b1, const float* __restrict__ W2, int n) {
    int warp = (int)(((size_t)blockIdx.x * blockDim.x + threadIdx.x) >> 5);
    int lane = threadIdx.x & 31;
    if (warp >= n) return;
    float s[NC];
#pragma unroll
    for (int c = 0; c < NC; c++) s[c] = 0.0f;
#pragma unroll
    for (int j = 0; j < 4; j++) {
        int f = lane + 32 * j;
        float v = g_out1[(size_t)warp * HID + f] + b1[f];
        float a = v > 0.0f ? v : expm1f(v);
#pragma unroll
        for (int c = 0; c < NC; c++) s[c] += a * W2[f * NC + c];
    }
#pragma unroll
    for (int off = 16; off > 0; off >>= 1)
#pragma unroll
        for (int c = 0; c < NC; c++) s[c] += __shfl_down_sync(0xffffffffu, s[c], off);
    if (lane == 0) {
#pragma unroll
        for (int c = 0; c < NC; c++) g_h2[(size_t)warp * 8 + c] = s[c];
        g_h2[(size_t)warp * 8 + 7] = 0.0f;
    }
}

// ---------------- self-loop init layer2 ----------------
__global__ void k_self2(int n) {
    size_t idx = (size_t)blockIdx.x * blockDim.x + threadIdx.x;
    if (idx < (size_t)n * 8) {
        int i = (int)(idx >> 3);
        float d = g_dinv[i];
        g_out2[idx] = g_h2[idx] * d * d;
    }
}

// ---------------- edge scatter layer 2: thread per edge, 2x red.v4 ----------------
__global__ void k_scatter2(const int* __restrict__ ei, const float* __restrict__ ew, int E) {
    int e = (int)((size_t)blockIdx.x * blockDim.x + threadIdx.x);
    if (e >= E) return;
    int s = ei[e];
    int d = ei[E + e];
    float norm = g_dinv[s] * ew[e] * g_dinv[d];
    float4 a = *(const float4*)(g_h2 + (size_t)s * 8);
    float4 b = *(const float4*)(g_h2 + (size_t)s * 8 + 4);
    float* p = g_out2 + (size_t)d * 8;
    asm volatile("red.global.add.v4.f32 [%0], {%1,%2,%3,%4};"
                 :: "l"(p), "f"(a.x * norm), "f"(a.y * norm), "f"(a.z * norm), "f"(a.w * norm)
                 : "memory");
    asm volatile("red.global.add.v4.f32 [%0], {%1,%2,%3,%4};"
                 :: "l"(p + 4), "f"(b.x * norm), "f"(b.y * norm), "f"(b.z * norm), "f"(b.w * norm)
                 : "memory");
}

// ---------------- bias + log_softmax ----------------
__global__ void k_softmax(const float* __restrict__ b2, float* __restrict__ out, int n) {
    int i = (int)((size_t)blockIdx.x * blockDim.x + threadIdx.x);
    if (i >= n) return;
    float4 a = *(const float4*)(g_out2 + (size_t)i * 8);
    float4 b = *(const float4*)(g_out2 + (size_t)i * 8 + 4);
    float z[NC];
    z[0] = a.x + b2[0]; z[1] = a.y + b2[1]; z[2] = a.z + b2[2]; z[3] = a.w + b2[3];
    z[4] = b.x + b2[4]; z[5] = b.y + b2[5]; z[6] = b.z + b2[6];
    float m = z[0];
#pragma unroll
    for (int c = 1; c < NC; c++) m = fmaxf(m, z[c]);
    float sum = 0.0f;
#pragma unroll
    for (int c = 0; c < NC; c++) sum += expf(z[c] - m);
    float lse = m + logf(sum);
#pragma unroll
    for (int c = 0; c < NC; c++) out[(size_t)i * NC + c] = z[c] - lse;
}

// ---------------- launcher ----------------
extern "C" void kernel_launch(void* const* d_in, const int* in_sizes, int n_in,
                              void* d_out, int out_size) {
    const float* x  = (const float*)d_in[0];
    const int*   ei = (const int*)d_in[1];
    const float* ew = (const float*)d_in[2];
    const float* W1 = (const float*)d_in[3];
    const float* b1 = (const float*)d_in[4];
    const float* W2 = (const float*)d_in[5];
    const float* b2 = (const float*)d_in[6];
    float* out = (float*)d_out;

    const int Nn = in_sizes[0] / IN_FEAT;   // 100000
    const int E  = in_sizes[2];             // 1600000

    k_deg_init<<<(Nn + 255) / 256, 256>>>(Nn);
    k_deg_acc<<<(E + 255) / 256, 256>>>(ei, ew, E);
    k_dinv<<<(Nn + 255) / 256, 256>>>(Nn);

    k_gemm1<<<(Nn + 127) / 128, 256>>>(x, W1, Nn);

    {
        size_t tot = (size_t)Nn * HID;
        k_self1<<<(int)((tot + 255) / 256), 256>>>(Nn);
    }
    k_scatter1<<<(E + 7) / 8, 256>>>(ei, ew, E);   // warp per edge

    k_fuse2<<<(Nn + 7) / 8, 256>>>(b1, W2, Nn);    // warp per node

    {
        size_t tot = (size_t)Nn * 8;
        k_self2<<<(int)((tot + 255) / 256), 256>>>(Nn);
    }
    k_scatter2<<<(E + 255) / 256, 256>>>(ei, ew, E);

    k_softmax<<<(Nn + 255) / 256, 256>>>(b2, out, Nn);
}

// round 3
// speedup vs baseline: 1.2040x; 1.2040x over previous
#include <cuda_runtime.h>
#include <cuda_bf16.h>
#include <mma.h>
#include <math.h>
#include <stdint.h>

using namespace nvcuda;

#define NN 100000
#define EE 1600000
#define IN_FEAT 512
#define HID 128
#define NC 7

#define BK 32
#define KPAD 48   // bf16 elems per row in smem tiles (96B, 16B-aligned rows)

// -------- scratch (device globals; allocation-free rule) --------
__device__ __align__(256) float g_dinv[NN];
__device__ __align__(256) float g_h1[(size_t)(NN + 128) * HID];  // +128 rows pad for unpredicated wmma stores
__device__ __align__(256) float g_out1[(size_t)NN * HID];
__device__ __align__(256) float g_h2[(size_t)NN * 8];
__device__ __align__(256) float g_out2[(size_t)NN * 8];
// W1^T split into bf16 hi/lo: [n][k]
__device__ __align__(256) __nv_bfloat16 g_WTh[HID * IN_FEAT];
__device__ __align__(256) __nv_bfloat16 g_WTl[HID * IN_FEAT];

// ---------------- degree ----------------
__global__ void k_deg_init(int n) {
    int i = blockIdx.x * blockDim.x + threadIdx.x;
    if (i < n) g_dinv[i] = 1.0f;
}
__global__ void k_deg_acc(const int* __restrict__ ei, const float* __restrict__ ew, int E) {
    int e = blockIdx.x * blockDim.x + threadIdx.x;
    if (e < E) atomicAdd(&g_dinv[ei[E + e]], ew[e]);
}
__global__ void k_dinv(int n) {
    int i = blockIdx.x * blockDim.x + threadIdx.x;
    if (i < n) {
        float d = g_dinv[i];
        g_dinv[i] = d > 0.0f ? rsqrtf(d) : 0.0f;
    }
}

// ---------------- W1 transpose + bf16 split ----------------
__global__ void k_wsplit(const float* __restrict__ W1) {
    int idx = blockIdx.x * blockDim.x + threadIdx.x;
    if (idx >= HID * IN_FEAT) return;
    int k = idx & (IN_FEAT - 1);
    int n = idx >> 9;
    float w = W1[k * HID + n];
    __nv_bfloat16 hi = __float2bfloat16(w);
    __nv_bfloat16 lo = __float2bfloat16(w - __bfloat162float(hi));
    g_WTh[n * IN_FEAT + k] = hi;
    g_WTl[n * IN_FEAT + k] = lo;
}

// ---------------- GEMM1: h1 = x @ W1 via bf16 WMMA, 3-pass split ----------------
// CTA: 128x128, 512 threads = 16 warps on a 4(M) x 4(N) grid of 32x32 warp tiles.
// K = 512 in 16 stages of 32, double buffered.
// smem layout (bf16 elems): [stage 0|1][Ah, Al, Bh, Bl], each 128 x KPAD.
#define TILE_ELEMS (128 * KPAD)
#define G1_SMEM (8 * TILE_ELEMS * 2)

__global__ void __launch_bounds__(512) k_gemm1_wmma(const float* __restrict__ A, int M) {
    extern __shared__ __align__(16) __nv_bfloat16 sm[];
    const int t = threadIdx.x;
    const int wid = t >> 5;
    const int wm = wid & 3;       // 0..3 -> rows wm*32
    const int wn = wid >> 2;      // 0..3 -> cols wn*32
    const int rowBase = blockIdx.x * 128;

    wmma::fragment<wmma::accumulator, 16, 16, 16, float> acc[2][2];
#pragma unroll
    for (int i = 0; i < 2; i++)
#pragma unroll
        for (int j = 0; j < 2; j++) wmma::fill_fragment(acc[i][j], 0.0f);

    // per-thread load indices
    // A: 128 rows x 32 k fp32 = 1024 float4; 2 per thread
    const int ar0 = t >> 3;                 // row for l=0 (0..63)... actually idx>>3
    // (compute inside helpers below)

    float4 avreg[2];
    uint4 bhreg, blreg;

    auto loadGlobal = [&](int c) {
#pragma unroll
        for (int l = 0; l < 2; l++) {
            int idx = t + l * 512;
            int r = idx >> 3;
            int g = idx & 7;
            float4 v = make_float4(0.f, 0.f, 0.f, 0.f);
            if (rowBase + r < M)
                v = *(const float4*)(A + (size_t)(rowBase + r) * IN_FEAT + c * BK + g * 4);
            avreg[l] = v;
        }
        {
            int n = t >> 2;
            int g = t & 3;
            const __nv_bfloat16* ph = g_WTh + (size_t)n * IN_FEAT + c * BK + g * 8;
            const __nv_bfloat16* pl = g_WTl + (size_t)n * IN_FEAT + c * BK + g * 8;
            bhreg = *(const uint4*)ph;
            blreg = *(const uint4*)pl;
        }
    };

    auto storeSmem = [&](int buf) {
        __nv_bfloat16* Ah = sm + (size_t)(buf * 4 + 0) * TILE_ELEMS;
        __nv_bfloat16* Al = sm + (size_t)(buf * 4 + 1) * TILE_ELEMS;
        __nv_bfloat16* Bh = sm + (size_t)(buf * 4 + 2) * TILE_ELEMS;
        __nv_bfloat16* Bl = sm + (size_t)(buf * 4 + 3) * TILE_ELEMS;
#pragma unroll
        for (int l = 0; l < 2; l++) {
            int idx = t + l * 512;
            int r = idx >> 3;
            int g = idx & 7;
            float4 v = avreg[l];
            __nv_bfloat16 hx = __float2bfloat16(v.x);
            __nv_bfloat16 hy = __float2bfloat16(v.y);
            __nv_bfloat16 hz = __float2bfloat16(v.z);
            __nv_bfloat16 hw = __float2bfloat16(v.w);
            __nv_bfloat16 lx = __float2bfloat16(v.x - __bfloat162float(hx));
            __nv_bfloat16 ly = __float2bfloat16(v.y - __bfloat162float(hy));
            __nv_bfloat16 lz = __float2bfloat16(v.z - __bfloat162float(hz));
            __nv_bfloat16 lw = __float2bfloat16(v.w - __bfloat162float(hw));
            int off = r * KPAD + g * 4;
            *(__nv_bfloat162*)(Ah + off)     = __nv_bfloat162(hx, hy);
            *(__nv_bfloat162*)(Ah + off + 2) = __nv_bfloat162(hz, hw);
            *(__nv_bfloat162*)(Al + off)     = __nv_bfloat162(lx, ly);
            *(__nv_bfloat162*)(Al + off + 2) = __nv_bfloat162(lz, lw);
        }
        {
            int n = t >> 2;
            int g = t & 3;
            int off = n * KPAD + g * 8;
            *(uint4*)(Bh + off) = bhreg;
            *(uint4*)(Bl + off) = blreg;
        }
    };

    auto compute = [&](int buf) {
        const __nv_bfloat16* Ah = sm + (size_t)(buf * 4 + 0) * TILE_ELEMS;
        const __nv_bfloat16* Al = sm + (size_t)(buf * 4 + 1) * TILE_ELEMS;
        const __nv_bfloat16* Bh = sm + (size_t)(buf * 4 + 2) * TILE_ELEMS;
        const __nv_bfloat16* Bl = sm + (size_t)(buf * 4 + 3) * TILE_ELEMS;
#pragma unroll
        for (int kk = 0; kk < BK; kk += 16) {
            wmma::fragment<wmma::matrix_a, 16, 16, 16, __nv_bfloat16, wmma::row_major> fah[2], fal[2];
            wmma::fragment<wmma::matrix_b, 16, 16, 16, __nv_bfloat16, wmma::col_major> fbh[2], fbl[2];
#pragma unroll
            for (int i = 0; i < 2; i++) {
                wmma::load_matrix_sync(fah[i], Ah + (wm * 32 + i * 16) * KPAD + kk, KPAD);
                wmma::load_matrix_sync(fal[i], Al + (wm * 32 + i * 16) * KPAD + kk, KPAD);
            }
#pragma unroll
            for (int j = 0; j < 2; j++) {
                wmma::load_matrix_sync(fbh[j], Bh + (wn * 32 + j * 16) * KPAD + kk, KPAD);
                wmma::load_matrix_sync(fbl[j], Bl + (wn * 32 + j * 16) * KPAD + kk, KPAD);
            }
#pragma unroll
            for (int i = 0; i < 2; i++)
#pragma unroll
                for (int j = 0; j < 2; j++) {
                    wmma::mma_sync(acc[i][j], fah[i], fbh[j], acc[i][j]);
                    wmma::mma_sync(acc[i][j], fal[i], fbh[j], acc[i][j]);
                    wmma::mma_sync(acc[i][j], fah[i], fbl[j], acc[i][j]);
                }
        }
    };

    loadGlobal(0);
    storeSmem(0);
    __syncthreads();

    const int NSTAGE = IN_FEAT / BK;  // 16
    for (int c = 0; c < NSTAGE; c++) {
        int buf = c & 1;
        if (c + 1 < NSTAGE) loadGlobal(c + 1);
        compute(buf);
        __syncthreads();
        if (c + 1 < NSTAGE) {
            storeSmem(1 - buf);
            __syncthreads();
        }
    }

    // epilogue: store h1 (g_h1 padded, tail CTA safe)
#pragma unroll
    for (int i = 0; i < 2; i++)
#pragma unroll
        for (int j = 0; j < 2; j++) {
            float* p = g_h1 + (size_t)(rowBase + wm * 32 + i * 16) * HID + wn * 32 + j * 16;
            wmma::store_matrix_sync(p, acc[i][j], HID, wmma::mem_row_major);
        }
}

// ---------------- self-loop init: out1 = h1 * dinv^2 ----------------
__global__ void k_self1(int n) {
    size_t idx = (size_t)blockIdx.x * blockDim.x + threadIdx.x;
    if (idx < (size_t)n * HID) {
        int i = (int)(idx >> 7);
        float d = g_dinv[i];
        g_out1[idx] = g_h1[idx] * d * d;
    }
}

// ---------------- edge scatter layer 1: warp per edge, red.v4 ----------------
__global__ void k_scatter1(const int* __restrict__ ei, const float* __restrict__ ew, int E) {
    int warp = (int)(((size_t)blockIdx.x * blockDim.x + threadIdx.x) >> 5);
    int lane = threadIdx.x & 31;
    if (warp >= E) return;
    int s = ei[warp];
    int d = ei[E + warp];
    float norm = g_dinv[s] * ew[warp] * g_dinv[d];
    float4 v = *((const float4*)(g_h1 + (size_t)s * HID) + lane);
    float* p = g_out1 + (size_t)d * HID + lane * 4;
    asm volatile("red.global.add.v4.f32 [%0], {%1,%2,%3,%4};"
                 :: "l"(p), "f"(v.x * norm), "f"(v.y * norm), "f"(v.z * norm), "f"(v.w * norm)
                 : "memory");
}

// ---------------- fused: h = elu(out1 + b1); h2 = h @ W2 (warp per node) ----------------
__global__ void k_fuse2(const float* __restrict__ b1, const float* __restrict__ W2, int n) {
    int warp = (int)(((size_t)blockIdx.x * blockDim.x + threadIdx.x) >> 5);
    int lane = threadIdx.x & 31;
    if (warp >= n) return;
    float s[NC];
#pragma unroll
    for (int c = 0; c < NC; c++) s[c] = 0.0f;
#pragma unroll
    for (int j = 0; j < 4; j++) {
        int f = lane + 32 * j;
        float v = g_out1[(size_t)warp * HID + f] + b1[f];
        float a = v > 0.0f ? v : expm1f(v);
#pragma unroll
        for (int c = 0; c < NC; c++) s[c] += a * W2[f * NC + c];
    }
#pragma unroll
    for (int off = 16; off > 0; off >>= 1)
#pragma unroll
        for (int c = 0; c < NC; c++) s[c] += __shfl_down_sync(0xffffffffu, s[c], off);
    if (lane == 0) {
#pragma unroll
        for (int c = 0; c < NC; c++) g_h2[(size_t)warp * 8 + c] = s[c];
        g_h2[(size_t)warp * 8 + 7] = 0.0f;
    }
}

// ---------------- self-loop init layer2 ----------------
__global__ void k_self2(int n) {
    size_t idx = (size_t)blockIdx.x * blockDim.x + threadIdx.x;
    if (idx < (size_t)n * 8) {
        int i = (int)(idx >> 3);
        float d = g_dinv[i];
        g_out2[idx] = g_h2[idx] * d * d;
    }
}

// ---------------- edge scatter layer 2: thread per edge, 2x red.v4 ----------------
__global__ void k_scatter2(const int* __restrict__ ei, const float* __restrict__ ew, int E) {
    int e = (int)((size_t)blockIdx.x * blockDim.x + threadIdx.x);
    if (e >= E) return;
    int s = ei[e];
    int d = ei[E + e];
    float norm = g_dinv[s] * ew[e] * g_dinv[d];
    float4 a = *(const float4*)(g_h2 + (size_t)s * 8);
    float4 b = *(const float4*)(g_h2 + (size_t)s * 8 + 4);
    float* p = g_out2 + (size_t)d * 8;
    asm volatile("red.global.add.v4.f32 [%0], {%1,%2,%3,%4};"
                 :: "l"(p), "f"(a.x * norm), "f"(a.y * norm), "f"(a.z * norm), "f"(a.w * norm)
                 : "memory");
    asm volatile("red.global.add.v4.f32 [%0], {%1,%2,%3,%4};"
                 :: "l"(p + 4), "f"(b.x * norm), "f"(b.y * norm), "f"(b.z * norm), "f"(b.w * norm)
                 : "memory");
}

// ---------------- bias + log_softmax ----------------
__global__ void k_softmax(const float* __restrict__ b2, float* __restrict__ out, int n) {
    int i = (int)((size_t)blockIdx.x * blockDim.x + threadIdx.x);
    if (i >= n) return;
    float4 a = *(const float4*)(g_out2 + (size_t)i * 8);
    float4 b = *(const float4*)(g_out2 + (size_t)i * 8 + 4);
    float z[NC];
    z[0] = a.x + b2[0]; z[1] = a.y + b2[1]; z[2] = a.z + b2[2]; z[3] = a.w + b2[3];
    z[4] = b.x + b2[4]; z[5] = b.y + b2[5]; z[6] = b.z + b2[6];
    float m = z[0];
#pragma unroll
    for (int c = 1; c < NC; c++) m = fmaxf(m, z[c]);
    float sum = 0.0f;
#pragma unroll
    for (int c = 0; c < NC; c++) sum += expf(z[c] - m);
    float lse = m + logf(sum);
#pragma unroll
    for (int c = 0; c < NC; c++) out[(size_t)i * NC + c] = z[c] - lse;
}

// ---------------- launcher ----------------
extern "C" void kernel_launch(void* const* d_in, const int* in_sizes, int n_in,
                              void* d_out, int out_size) {
    const float* x  = (const float*)d_in[0];
    const int*   ei = (const int*)d_in[1];
    const float* ew = (const float*)d_in[2];
    const float* W1 = (const float*)d_in[3];
    const float* b1 = (const float*)d_in[4];
    const float* W2 = (const float*)d_in[5];
    const float* b2 = (const float*)d_in[6];
    float* out = (float*)d_out;

    const int Nn = in_sizes[0] / IN_FEAT;   // 100000
    const int E  = in_sizes[2];             // 1600000

    k_deg_init<<<(Nn + 255) / 256, 256>>>(Nn);
    k_deg_acc<<<(E + 255) / 256, 256>>>(ei, ew, E);
    k_dinv<<<(Nn + 255) / 256, 256>>>(Nn);

    k_wsplit<<<(HID * IN_FEAT + 255) / 256, 256>>>(W1);

    static int smem_set = 0;
    if (!smem_set) {
        cudaFuncSetAttribute(k_gemm1_wmma, cudaFuncAttributeMaxDynamicSharedMemorySize, G1_SMEM);
        smem_set = 1;
    }
    k_gemm1_wmma<<<(Nn + 127) / 128, 512, G1_SMEM>>>(x, Nn);

    {
        size_t tot = (size_t)Nn * HID;
        k_self1<<<(int)((tot + 255) / 256), 256>>>(Nn);
    }
    k_scatter1<<<(E + 7) / 8, 256>>>(ei, ew, E);   // warp per edge

    k_fuse2<<<(Nn + 7) / 8, 256>>>(b1, W2, Nn);    // warp per node

    {
        size_t tot = (size_t)Nn * 8;
        k_self2<<<(int)((tot + 255) / 256), 256>>>(Nn);
    }
    k_scatter2<<<(E + 255) / 256, 256>>>(ei, ew, E);

    k_softmax<<<(Nn + 255) / 256, 256>>>(b2, out, Nn);
}